// round 14
// baseline (speedup 1.0000x reference)
#include <cuda_runtime.h>
#include <cuda_bf16.h>
#include <cstdint>
#include <math.h>

// ---------------------------------------------------------------------------
// BackbonePointNet on GB300, round 14 = R13 + bf16 intermediates.
// R13 ncu: l1tex 71% dominated by producer gather LDG (fp32 A rows) -> store
// A/h1/h2 in bf16: gather bytes halve, producer convert collapses to
// sub.rn.bf16x2 + max.bf16x2 (P pre-packed bf16x2). h3 stays fp32 for pool.
// Engine otherwise identical to R13 (ldmatrix frags, 2-term W split,
// warp-specialized producer/consumer, K-folded node GEMMs, fragment seg-max).
// ---------------------------------------------------------------------------

#define MAXN 100000
__device__ __nv_bfloat16 g_A[MAXN * 128];
__device__ __nv_bfloat16 g_h1[MAXN * 64];
__device__ __nv_bfloat16 g_h2[MAXN * 64];
__device__ float g_h3[MAXN * 128];
__device__ float g_part[64 * 8 * 128];
__device__ float g_pool[64 * 128];

// --------------------------- small asm helpers ------------------------------
__device__ __forceinline__ void mma16816(float* c, const uint32_t* a,
                                         uint32_t b0, uint32_t b1) {
    asm volatile(
        "mma.sync.aligned.m16n8k16.row.col.f32.bf16.bf16.f32 "
        "{%0,%1,%2,%3}, {%4,%5,%6,%7}, {%8,%9}, {%0,%1,%2,%3};"
        : "+f"(c[0]), "+f"(c[1]), "+f"(c[2]), "+f"(c[3])
        : "r"(a[0]), "r"(a[1]), "r"(a[2]), "r"(a[3]), "r"(b0), "r"(b1));
}

__device__ __forceinline__ void ldsm_x4(uint32_t* d, uint32_t addr) {
    asm volatile(
        "ldmatrix.sync.aligned.m8n8.x4.shared.b16 {%0,%1,%2,%3}, [%4];"
        : "=r"(d[0]), "=r"(d[1]), "=r"(d[2]), "=r"(d[3]) : "r"(addr));
}

__device__ __forceinline__ uint32_t smem_u32(const void* p) {
    uint32_t a;
    asm("{ .reg .u64 t; cvta.to.shared.u64 t, %1; cvt.u32.u64 %0, t; }"
        : "=r"(a) : "l"(p));
    return a;
}

// relu(a - p) on packed bf16x2.
__device__ __forceinline__ uint32_t sub_relu_bf16x2(uint32_t a, uint32_t p) {
    uint32_t d;
    asm("sub.rn.bf16x2 %0, %1, %2;" : "=r"(d) : "r"(a), "r"(p));
    asm("max.bf16x2 %0, %1, %2;" : "=r"(d) : "r"(d), "r"(0u));
    return d;
}
__device__ __forceinline__ uint32_t pack_bf16(float a0, float a1) {
    uint32_t h;
    asm("cvt.rn.bf16x2.f32 %0, %1, %2;" : "=r"(h) : "f"(a1), "f"(a0));
    return h;
}

__device__ __forceinline__ unsigned long long pk2(float lo, float hi) {
    unsigned long long d;
    asm("mov.b64 %0, {%1, %2};" : "=l"(d)
        : "r"(__float_as_uint(lo)), "r"(__float_as_uint(hi)));
    return d;
}
__device__ __forceinline__ void upk2(unsigned long long v, float& lo, float& hi) {
    unsigned int a, b;
    asm("mov.b64 {%0, %1}, %2;" : "=r"(a), "=r"(b) : "l"(v));
    lo = __uint_as_float(a);
    hi = __uint_as_float(b);
}
__device__ __forceinline__ unsigned long long ffma2(unsigned long long a,
                                                    unsigned long long b,
                                                    unsigned long long c) {
    unsigned long long d;
    asm("fma.rn.f32x2 %0, %1, %2, %3;" : "=l"(d) : "l"(a), "l"(b), "l"(c));
    return d;
}

// ---------------------------------------------------------------------------
// Layer-1 node GEMM (K=6, tiny): fp32 SIMT, bf16 output.
// ---------------------------------------------------------------------------
template <int HC, int H>
__global__ __launch_bounds__(256)
void node_kernel(const float* __restrict__ hin, const float* __restrict__ pos,
                 const float* __restrict__ Wa, const float* __restrict__ ba,
                 __nv_bfloat16* __restrict__ A, int N) {
    constexpr int CIN  = HC + 3;
    constexpr int CINP = (CIN + 3) & ~3;
    extern __shared__ float sm[];
    float* Xs = sm;
    float* Ws = Xs + 128 * CINP;
    const int tid = threadIdx.x;
    const int n0  = blockIdx.x * 128;

    for (int idx = tid; idx < CINP * H; idx += 256) {
        int k = idx / H, c = idx - k * H;
        Ws[idx] = (k < CIN) ? Wa[k * H + c] : 0.f;
    }
    for (int idx = tid; idx < 128 * CINP; idx += 256) {
        int r = idx / CINP, k = idx - r * CINP;
        int n = n0 + r;
        float v = 0.f;
        if (n < N) {
            if (k < HC) v = hin[n * HC + k];
            else if (k < CIN) v = pos[n * 3 + (k - HC)];
        }
        Xs[idx] = v;
    }
    __syncthreads();

    const int tx = tid & 15, ty = tid >> 4;
    for (int cb = 0; cb < H; cb += 64) {
        unsigned long long acc[8][2];
#pragma unroll
        for (int j = 0; j < 2; ++j) {
            unsigned long long bv =
                *(const unsigned long long*)(ba + cb + 2 * (tx + 16 * j));
#pragma unroll
            for (int i = 0; i < 8; ++i) acc[i][j] = bv;
        }
#pragma unroll 4
        for (int k = 0; k < CINP; ++k) {
            unsigned long long w0 =
                *(const unsigned long long*)(Ws + k * H + cb + 2 * tx);
            unsigned long long w1 =
                *(const unsigned long long*)(Ws + k * H + cb + 2 * (tx + 16));
#pragma unroll
            for (int i = 0; i < 8; ++i) {
                float x = Xs[(ty + 16 * i) * CINP + k];
                unsigned long long xp = pk2(x, x);
                acc[i][0] = ffma2(xp, w0, acc[i][0]);
                acc[i][1] = ffma2(xp, w1, acc[i][1]);
            }
        }
#pragma unroll
        for (int i = 0; i < 8; ++i) {
            int n = n0 + ty + 16 * i;
            if (n < N) {
#pragma unroll
                for (int j = 0; j < 2; ++j) {
                    float lo, hi;
                    upk2(acc[i][j], lo, hi);
                    *(uint32_t*)(A + (size_t)n * H + cb + 2 * (tx + 16 * j)) =
                        pack_bf16(lo, hi);
                }
            }
        }
    }
}

// ---------------------------------------------------------------------------
// Node GEMM via WS-HMMA: A[n] = [h, pos, 1, pad] @ [Wa; ba; 0] (K folded).
// hin bf16 (copied straight to smem), A out bf16.
// ---------------------------------------------------------------------------
template <int HC, int H, int MAXB>
__global__ __launch_bounds__(256, MAXB)
void node_mma_kernel(const __nv_bfloat16* __restrict__ hin,
                     const float* __restrict__ pos,
                     const float* __restrict__ Wa, const float* __restrict__ ba,
                     __nv_bfloat16* __restrict__ A, int N, int tiles) {
    constexpr int CIN = HC + 3;
    constexpr int KT  = ((HC + 4 + 15) / 16) * 16;  // 80 for HC=64
    constexpr int KC  = KT / 16;
    constexpr int RS  = KT * 2 + 16;   // X row bytes
    constexpr int SX  = KT + 8;        // W padded row (bf16)
    constexpr int NB  = H / 8;
    constexpr int PW  = 4;

    extern __shared__ char smem[];
    char* Xb[2] = {smem, smem + 128 * RS};
    __nv_bfloat16* Wh = (__nv_bfloat16*)(smem + 2 * 128 * RS);
    __nv_bfloat16* Wl = Wh + H * SX;

    const int tid = threadIdx.x, wid = tid >> 5, lane = tid & 31;
    const int r = lane >> 2, q = lane & 3;
    const bool isProd = wid < PW;

    for (int idx = tid; idx < KT * H; idx += 256) {
        int k = idx / H, c = idx - k * H;
        float w = (k < CIN) ? Wa[k * H + c] : ((k == CIN) ? ba[c] : 0.f);
        __nv_bfloat16 hb = __float2bfloat16(w);
        __nv_bfloat16 lb = __float2bfloat16(w - __bfloat162float(hb));
        Wh[c * SX + k] = hb;
        Wl[c * SX + k] = lb;
    }

    auto produce = [&](int t, char* Xbuf) {
        const int base = wid * 32;
#pragma unroll
        for (int p = 0; p < 16; ++p) {
            int row = base + 2 * p + (lane >> 4);
            int c4  = lane & 15;
            int n   = t * 128 + row;
            uint2 a = make_uint2(0u, 0u);
            if (n < N) a = *(const uint2*)(hin + (size_t)n * HC + 4 * c4);
            *(uint2*)(Xbuf + row * RS + c4 * 8) = a;
        }
#pragma unroll
        for (int p = 0; p < (KT - HC) / 4; ++p) {
            int row = base + lane;
            int n   = t * 128 + row;
            float4 v = make_float4(0.f, 0.f, 0.f, 0.f);
            if (p == 0) {
                int nn = (n < N) ? n : (N - 1);
                v.x = pos[nn * 3]; v.y = pos[nn * 3 + 1]; v.z = pos[nn * 3 + 2];
                v.w = 1.f;
            }
            *(uint2*)(Xbuf + row * RS + (HC / 4 + p) * 8) =
                make_uint2(pack_bf16(v.x, v.y), pack_bf16(v.z, v.w));
        }
    };

    auto consume = [&](int t, const char* Xbuf) {
        const int cw = wid - PW;
        const uint32_t Xu  = smem_u32(Xbuf);
        const uint32_t WhU = smem_u32(Wh), WlU = smem_u32(Wl);
        const int arow  = (lane & 7) + 8 * ((lane >> 3) & 1);
        const int ahalf = (lane >> 4) * 16;
        const int bsel  = lane >> 3;
        const uint32_t bbase = ((bsel < 2) ? WhU : WlU) +
                               (uint32_t)((lane & 7) * SX * 2) + (bsel & 1) * 16;

        uint32_t ah[2][KC][4];
#pragma unroll
        for (int mt = 0; mt < 2; ++mt) {
            uint32_t abase = Xu +
                (uint32_t)((16 * (cw * 2 + mt) + arow) * RS) + ahalf;
#pragma unroll
            for (int kc = 0; kc < KC; ++kc)
                ldsm_x4(ah[mt][kc], abase + 32 * kc);
        }

        uint32_t bf[2][4];
        ldsm_x4(bf[0], bbase);
#pragma unroll
        for (int nb = 0; nb < NB; ++nb) {
            float acc[2][2][4];
#pragma unroll
            for (int mt = 0; mt < 2; ++mt)
#pragma unroll
                for (int ch = 0; ch < 2; ++ch)
#pragma unroll
                    for (int i = 0; i < 4; ++i) acc[mt][ch][i] = 0.f;
#pragma unroll
            for (int kc = 0; kc < KC; ++kc) {
                const int cur = (nb * KC + kc) & 1;
                {
                    int nnb = nb, nkc = kc + 1;
                    if (nkc == KC) { nkc = 0; nnb = (nb + 1 < NB) ? nb + 1 : nb; }
                    ldsm_x4(bf[cur ^ 1],
                            bbase + (uint32_t)(8 * nnb * SX * 2 + 32 * nkc));
                }
                const uint32_t* b = bf[cur];
#pragma unroll
                for (int mt = 0; mt < 2; ++mt) {
                    mma16816(acc[mt][0], ah[mt][kc], b[0], b[1]);
                    mma16816(acc[mt][1], ah[mt][kc], b[2], b[3]);
                }
            }
#pragma unroll
            for (int mt = 0; mt < 2; ++mt) {
                int nbase = t * 128 + 16 * (cw * 2 + mt);
                int col = 8 * nb + 2 * q;
                int nA = nbase + r, nBr = nbase + r + 8;
                if (nA < N)
                    *(uint32_t*)(A + (size_t)nA * H + col) =
                        pack_bf16(acc[mt][0][0] + acc[mt][1][0],
                                  acc[mt][0][1] + acc[mt][1][1]);
                if (nBr < N)
                    *(uint32_t*)(A + (size_t)nBr * H + col) =
                        pack_bf16(acc[mt][0][2] + acc[mt][1][2],
                                  acc[mt][0][3] + acc[mt][1][3]);
            }
        }
    };

    __syncthreads();
    const int t0 = blockIdx.x;
    if (isProd) produce(t0, Xb[0]);
    __syncthreads();

    for (int k = 0;; ++k) {
        int tc = t0 + k * gridDim.x;
        if (tc >= tiles) break;
        if (isProd) {
            int tp = tc + gridDim.x;
            if (tp < tiles) produce(tp, Xb[(k + 1) & 1]);
        } else {
            consume(tc, Xb[k & 1]);
        }
        __syncthreads();
    }
}

// ---------------------------------------------------------------------------
// Warp-specialized edge kernel: bf16 A gather, sub/relu in bf16x2, ldmatrix
// fragments, 2-term W split, fragment seg-max. OBF16 selects output dtype.
// ---------------------------------------------------------------------------
template <int H, int COUT, int TPB, int MAXB, bool OBF16>
__global__ __launch_bounds__(TPB, MAXB)
void edge_ws_kernel(const __nv_bfloat16* __restrict__ A,
                    const float* __restrict__ pos,
                    const int* __restrict__ src, const float* __restrict__ Wap,
                    const float* __restrict__ Wb, const float* __restrict__ bb,
                    void* __restrict__ hout, int N, int E, int tiles) {
    constexpr int WARPS = TPB / 32;
    constexpr int PW    = WARPS / 2;
    constexpr int NPN   = 2;
    constexpr int NODES = PW * NPN;
    constexpr int ROWS  = NODES * 16;
    constexpr int KC    = H / 16;
    constexpr int NB    = COUT / 8;
    constexpr int RS    = H * 2 + 16;
    constexpr int SX    = H + 8;

    extern __shared__ char smem[];
    char* Xb[2] = {smem, smem + ROWS * RS};
    __nv_bfloat16* Wh = (__nv_bfloat16*)(smem + 2 * ROWS * RS);
    __nv_bfloat16* Wl = Wh + COUT * SX;

    const int tid = threadIdx.x, wid = tid >> 5, lane = tid & 31;
    const bool isProd = wid < PW;

    for (int idx = tid; idx < H * COUT; idx += TPB) {
        int k = idx / COUT, n = idx - k * COUT;
        float w = Wb[idx];
        __nv_bfloat16 hb = __float2bfloat16(w);
        __nv_bfloat16 lb = __float2bfloat16(w - __bfloat162float(hb));
        Wh[n * SX + k] = hb;
        Wl[n * SX + k] = lb;
    }

    auto produce = [&](int t, char* Xbuf) {
        const int e0 = t * ROWS, n0t = t * NODES;
        const int pw = wid;
#pragma unroll
        for (int nn = 0; nn < NPN; ++nn) {
            const int g  = pw * NPN + nn;
            const int nd = min(n0t + g, N - 1);
            int e = e0 + 16 * g + (lane & 15);
            int srcv = (e < E) ? src[e] : 0;
            const int c4 = (H == 64) ? (lane & 15) : lane;
            float p0 = pos[nd * 3], p1 = pos[nd * 3 + 1], p2 = pos[nd * 3 + 2];
            float P0 = p0 * __ldg(&Wap[4 * c4 + 0]) + p1 * __ldg(&Wap[H + 4 * c4 + 0]) +
                       p2 * __ldg(&Wap[2 * H + 4 * c4 + 0]);
            float P1 = p0 * __ldg(&Wap[4 * c4 + 1]) + p1 * __ldg(&Wap[H + 4 * c4 + 1]) +
                       p2 * __ldg(&Wap[2 * H + 4 * c4 + 1]);
            float P2 = p0 * __ldg(&Wap[4 * c4 + 2]) + p1 * __ldg(&Wap[H + 4 * c4 + 2]) +
                       p2 * __ldg(&Wap[2 * H + 4 * c4 + 2]);
            float P3 = p0 * __ldg(&Wap[4 * c4 + 3]) + p1 * __ldg(&Wap[H + 4 * c4 + 3]) +
                       p2 * __ldg(&Wap[2 * H + 4 * c4 + 3]);
            uint32_t P01 = pack_bf16(P0, P1), P23 = pack_bf16(P2, P3);
            constexpr int PASSES = (H == 64) ? 8 : 16;
#pragma unroll
            for (int p = 0; p < PASSES; ++p) {
                int rowin = (H == 64) ? (2 * p + (lane >> 4)) : p;
                int j = __shfl_sync(0xffffffffu, srcv, rowin);
                uint2 av = *(const uint2*)(A + (size_t)j * H + 4 * c4);
                uint32_t x01 = sub_relu_bf16x2(av.x, P01);
                uint32_t x23 = sub_relu_bf16x2(av.y, P23);
                int row = 16 * g + rowin;
                *(uint2*)(Xbuf + row * RS + c4 * 8) = make_uint2(x01, x23);
            }
        }
    };

    auto consume = [&](int t, const char* Xbuf) {
        const int n0t = t * NODES;
        const int cw  = wid - PW;
        const uint32_t Xu  = smem_u32(Xbuf);
        const uint32_t WhU = smem_u32(Wh), WlU = smem_u32(Wl);
        const int arow  = (lane & 7) + 8 * ((lane >> 3) & 1);
        const int ahalf = (lane >> 4) * 16;
        const int bsel  = lane >> 3;
        const uint32_t bbase = ((bsel < 2) ? WhU : WlU) +
                               (uint32_t)((lane & 7) * SX * 2) + (bsel & 1) * 16;

        uint32_t ah[NPN][KC][4];
#pragma unroll
        for (int nn = 0; nn < NPN; ++nn) {
            uint32_t abase = Xu +
                (uint32_t)((16 * (cw * NPN + nn) + arow) * RS) + ahalf;
#pragma unroll
            for (int kc = 0; kc < KC; ++kc)
                ldsm_x4(ah[nn][kc], abase + 32 * kc);
        }

        uint32_t bf[2][4];
        ldsm_x4(bf[0], bbase);
#pragma unroll
        for (int nb = 0; nb < NB; ++nb) {
            float acc[NPN][2][4];
#pragma unroll
            for (int nn = 0; nn < NPN; ++nn)
#pragma unroll
                for (int ch = 0; ch < 2; ++ch)
#pragma unroll
                    for (int i = 0; i < 4; ++i) acc[nn][ch][i] = 0.f;
#pragma unroll
            for (int kc = 0; kc < KC; ++kc) {
                const int cur = (nb * KC + kc) & 1;
                {
                    int nnb = nb, nkc = kc + 1;
                    if (nkc == KC) { nkc = 0; nnb = (nb + 1 < NB) ? nb + 1 : nb; }
                    ldsm_x4(bf[cur ^ 1],
                            bbase + (uint32_t)(8 * nnb * SX * 2 + 32 * nkc));
                }
                const uint32_t* b = bf[cur];
#pragma unroll
                for (int nn = 0; nn < NPN; ++nn) {
                    mma16816(acc[nn][0], ah[nn][kc], b[0], b[1]);
                    mma16816(acc[nn][1], ah[nn][kc], b[2], b[3]);
                }
            }
#pragma unroll
            for (int nn = 0; nn < NPN; ++nn) {
                float s0 = acc[nn][0][0] + acc[nn][1][0];
                float s1 = acc[nn][0][1] + acc[nn][1][1];
                float s2 = acc[nn][0][2] + acc[nn][1][2];
                float s3 = acc[nn][0][3] + acc[nn][1][3];
                float m0 = fmaxf(s0, s2);
                float m1 = fmaxf(s1, s3);
                m0 = fmaxf(m0, __shfl_xor_sync(0xffffffffu, m0, 4));
                m1 = fmaxf(m1, __shfl_xor_sync(0xffffffffu, m1, 4));
                m0 = fmaxf(m0, __shfl_xor_sync(0xffffffffu, m0, 8));
                m1 = fmaxf(m1, __shfl_xor_sync(0xffffffffu, m1, 8));
                m0 = fmaxf(m0, __shfl_xor_sync(0xffffffffu, m0, 16));
                m1 = fmaxf(m1, __shfl_xor_sync(0xffffffffu, m1, 16));
                int node = n0t + cw * NPN + nn;
                if (lane < 4 && node < N) {
                    int col = 8 * nb + 2 * lane;
                    float o0 = fmaxf(m0 + __ldg(&bb[col]), 0.f);
                    float o1 = fmaxf(m1 + __ldg(&bb[col + 1]), 0.f);
                    if (OBF16) {
                        *(uint32_t*)((__nv_bfloat16*)hout +
                                     (size_t)node * COUT + col) = pack_bf16(o0, o1);
                    } else {
                        *(float2*)((float*)hout + (size_t)node * COUT + col) =
                            make_float2(o0, o1);
                    }
                }
            }
        }
    };

    __syncthreads();
    const int t0 = blockIdx.x;
    if (isProd) produce(t0, Xb[0]);
    __syncthreads();

    for (int k = 0;; ++k) {
        int tc = t0 + k * gridDim.x;
        if (tc >= tiles) break;
        if (isProd) {
            int tp = tc + gridDim.x;
            if (tp < tiles) produce(tp, Xb[(k + 1) & 1]);
        } else {
            consume(tc, Xb[k & 1]);
        }
        __syncthreads();
    }
}

// ---------------------------------------------------------------------------
// Deterministic two-stage mean pool (batch sorted) + regressor.
// ---------------------------------------------------------------------------
__device__ __forceinline__ int lb(const int* __restrict__ b, int n, int v) {
    int lo = 0, hi = n;
    while (lo < hi) {
        int m = (lo + hi) >> 1;
        if (b[m] < v) lo = m + 1; else hi = m;
    }
    return lo;
}

__global__ void pool1_kernel(const float* __restrict__ h3,
                             const int* __restrict__ batch, int N,
                             float* __restrict__ part) {
    int b = blockIdx.x, k = blockIdx.y, c = threadIdx.x;
    int s = lb(batch, N, b), e = lb(batch, N, b + 1);
    int len = e - s;
    int cs = s + (int)(((long long)len * k) >> 3);
    int ce = s + (int)(((long long)len * (k + 1)) >> 3);
    float s0 = 0.f, s1 = 0.f, s2 = 0.f, s3 = 0.f;
    int n = cs;
    for (; n + 3 < ce; n += 4) {
        s0 += h3[(n + 0) * 128 + c];
        s1 += h3[(n + 1) * 128 + c];
        s2 += h3[(n + 2) * 128 + c];
        s3 += h3[(n + 3) * 128 + c];
    }
    for (; n < ce; ++n) s0 += h3[n * 128 + c];
    part[(b * 8 + k) * 128 + c] = ((s0 + s1) + (s2 + s3));
}

__global__ void pool2_kernel(const float* __restrict__ part,
                             const int* __restrict__ batch, int N,
                             float* __restrict__ pool) {
    int b = blockIdx.x, c = threadIdx.x;
    int s = lb(batch, N, b), e = lb(batch, N, b + 1);
    float sum = 0.f;
#pragma unroll
    for (int k = 0; k < 8; ++k) sum += part[(b * 8 + k) * 128 + c];
    pool[b * 128 + c] = sum / fmaxf((float)(e - s), 1.f);
}

__global__ void reg_kernel(const float* __restrict__ pool,
                           const float* __restrict__ wr1, const float* __restrict__ br1,
                           const float* __restrict__ wr2, const float* __restrict__ br2,
                           float* __restrict__ out, int B) {
    int b = blockIdx.x * blockDim.x + threadIdx.x;
    if (b >= B) return;
    float o = br2[0];
    for (int j = 0; j < 64; ++j) {
        float s = br1[j];
        for (int k = 0; k < 128; ++k) s += pool[b * 128 + k] * wr1[k * 64 + j];
        o += s * wr2[j];
    }
    out[b] = 1.f / (1.f + expf(-o));
}

extern "C" void kernel_launch(void* const* d_in, const int* in_sizes, int n_in,
                              void* d_out, int out_size) {
    const float* pos   = (const float*)d_in[0];
    const int*   ei    = (const int*)d_in[1];
    const int*   batch = (const int*)d_in[2];
    const float* w1a = (const float*)d_in[4],  *b1a = (const float*)d_in[5];
    const float* w1b = (const float*)d_in[6],  *b1b = (const float*)d_in[7];
    const float* w2a = (const float*)d_in[8],  *b2a = (const float*)d_in[9];
    const float* w2b = (const float*)d_in[10], *b2b = (const float*)d_in[11];
    const float* w3a = (const float*)d_in[12], *b3a = (const float*)d_in[13];
    const float* w3b = (const float*)d_in[14], *b3b = (const float*)d_in[15];
    const float* wr1 = (const float*)d_in[16], *br1 = (const float*)d_in[17];
    const float* wr2 = (const float*)d_in[18], *br2 = (const float*)d_in[19];
    float* out = (float*)d_out;

    int N = in_sizes[0] / 3;
    int E = in_sizes[1] / 2;
    int B = out_size;
    const int* srcp = ei;

    __nv_bfloat16 *Abuf, *h1, *h2;
    float *h3, *part, *pl;
    cudaGetSymbolAddress((void**)&Abuf, g_A);
    cudaGetSymbolAddress((void**)&h1, g_h1);
    cudaGetSymbolAddress((void**)&h2, g_h2);
    cudaGetSymbolAddress((void**)&h3, g_h3);
    cudaGetSymbolAddress((void**)&part, g_part);
    cudaGetSymbolAddress((void**)&pl, g_pool);

    const int smemN1 = (128 * 8 + 8 * 64) * 4;
    const int smemNM2 = 2 * 128 * 176 + 2 * 64 * 88 * 2;    //  67584
    const int smemNM3 = 2 * 128 * 176 + 2 * 128 * 88 * 2;   //  90112
    const int smemE12 = 2 * 128 * (64 * 2 + 16) + 2 * 64 * 72 * 2;    //  55296
    const int smemE3  = 2 * 256 * (128 * 2 + 16) + 2 * 128 * 136 * 2; // 208896

    cudaFuncSetAttribute(node_kernel<3, 64>,
                         cudaFuncAttributeMaxDynamicSharedMemorySize, smemN1);
    cudaFuncSetAttribute(node_mma_kernel<64, 64, 3>,
                         cudaFuncAttributeMaxDynamicSharedMemorySize, smemNM2);
    cudaFuncSetAttribute(node_mma_kernel<64, 128, 2>,
                         cudaFuncAttributeMaxDynamicSharedMemorySize, smemNM3);
    cudaFuncSetAttribute(edge_ws_kernel<64, 64, 256, 3, true>,
                         cudaFuncAttributeMaxDynamicSharedMemorySize, smemE12);
    cudaFuncSetAttribute(edge_ws_kernel<128, 128, 512, 1, false>,
                         cudaFuncAttributeMaxDynamicSharedMemorySize, smemE3);

    int tilesN = (N + 127) / 128;
    int tilesE12 = (E + 127) / 128;
    int tilesE3  = (E + 255) / 256;
    int gridN2 = tilesN < 444 ? tilesN : 444;
    int gridN3 = tilesN < 296 ? tilesN : 296;
    int grid12 = tilesE12 < 444 ? tilesE12 : 444;
    int grid3  = tilesE3 < 148 ? tilesE3 : 148;

    // layer 1 (h = pos)
    node_kernel<3, 64><<<tilesN, 256, smemN1>>>(pos, pos, w1a, b1a, Abuf, N);
    edge_ws_kernel<64, 64, 256, 3, true><<<grid12, 256, smemE12>>>(
        Abuf, pos, srcp, w1a + 3 * 64, w1b, b1b, h1, N, E, tilesE12);
    // layer 2
    node_mma_kernel<64, 64, 3><<<gridN2, 256, smemNM2>>>(
        h1, pos, w2a, b2a, Abuf, N, tilesN);
    edge_ws_kernel<64, 64, 256, 3, true><<<grid12, 256, smemE12>>>(
        Abuf, pos, srcp, w2a + 64 * 64, w2b, b2b, h2, N, E, tilesE12);
    // layer 3
    node_mma_kernel<64, 128, 2><<<gridN3, 256, smemNM3>>>(
        h2, pos, w3a, b3a, Abuf, N, tilesN);
    edge_ws_kernel<128, 128, 512, 1, false><<<grid3, 512, smemE3>>>(
        Abuf, pos, srcp, w3a + 64 * 128, w3b, b3b, h3, N, E, tilesE3);
    // pool + regressor
    pool1_kernel<<<dim3(B, 8), 128>>>(h3, batch, N, part);
    pool2_kernel<<<B, 128>>>(part, batch, N, pl);
    reg_kernel<<<1, 64>>>(pl, wr1, br1, wr2, br2, out, B);
}

// round 16
// speedup vs baseline: 1.1726x; 1.1726x over previous
#include <cuda_runtime.h>
#include <cuda_bf16.h>
#include <cstdint>
#include <math.h>

// ---------------------------------------------------------------------------
// BackbonePointNet on GB300, round 16 = R15 + smem OOB fix.
// R15 fault: node_mma paired-B ldmatrix prefetch let lane-group 3 read 16B
// past the end of Wh (last smem region) on the final n-block. Fix: +256B
// slack after Wh in every MMA kernel's smem allocation.
// Design: pure bf16 HMMA (C = bf16(X) @ bf16(W)); B-frag ldmatrix loads TWO
// kc per x4; warp-specialized producer/consumer, bf16 intermediates,
// K-folded node GEMMs, fragment seg-max.
// ---------------------------------------------------------------------------

#define MAXN 100000
__device__ __nv_bfloat16 g_A[MAXN * 128];
__device__ __nv_bfloat16 g_h1[MAXN * 64];
__device__ __nv_bfloat16 g_h2[MAXN * 64];
__device__ float g_h3[MAXN * 128];
__device__ float g_part[64 * 8 * 128];
__device__ float g_pool[64 * 128];

// --------------------------- small asm helpers ------------------------------
__device__ __forceinline__ void mma16816(float* c, const uint32_t* a,
                                         uint32_t b0, uint32_t b1) {
    asm volatile(
        "mma.sync.aligned.m16n8k16.row.col.f32.bf16.bf16.f32 "
        "{%0,%1,%2,%3}, {%4,%5,%6,%7}, {%8,%9}, {%0,%1,%2,%3};"
        : "+f"(c[0]), "+f"(c[1]), "+f"(c[2]), "+f"(c[3])
        : "r"(a[0]), "r"(a[1]), "r"(a[2]), "r"(a[3]), "r"(b0), "r"(b1));
}

__device__ __forceinline__ void ldsm_x4(uint32_t* d, uint32_t addr) {
    asm volatile(
        "ldmatrix.sync.aligned.m8n8.x4.shared.b16 {%0,%1,%2,%3}, [%4];"
        : "=r"(d[0]), "=r"(d[1]), "=r"(d[2]), "=r"(d[3]) : "r"(addr));
}

__device__ __forceinline__ uint32_t smem_u32(const void* p) {
    uint32_t a;
    asm("{ .reg .u64 t; cvta.to.shared.u64 t, %1; cvt.u32.u64 %0, t; }"
        : "=r"(a) : "l"(p));
    return a;
}

__device__ __forceinline__ uint32_t sub_relu_bf16x2(uint32_t a, uint32_t p) {
    uint32_t d;
    asm("sub.rn.bf16x2 %0, %1, %2;" : "=r"(d) : "r"(a), "r"(p));
    asm("max.bf16x2 %0, %1, %2;" : "=r"(d) : "r"(d), "r"(0u));
    return d;
}
__device__ __forceinline__ uint32_t pack_bf16(float a0, float a1) {
    uint32_t h;
    asm("cvt.rn.bf16x2.f32 %0, %1, %2;" : "=r"(h) : "f"(a1), "f"(a0));
    return h;
}

__device__ __forceinline__ unsigned long long pk2(float lo, float hi) {
    unsigned long long d;
    asm("mov.b64 %0, {%1, %2};" : "=l"(d)
        : "r"(__float_as_uint(lo)), "r"(__float_as_uint(hi)));
    return d;
}
__device__ __forceinline__ void upk2(unsigned long long v, float& lo, float& hi) {
    unsigned int a, b;
    asm("mov.b64 {%0, %1}, %2;" : "=r"(a), "=r"(b) : "l"(v));
    lo = __uint_as_float(a);
    hi = __uint_as_float(b);
}
__device__ __forceinline__ unsigned long long ffma2(unsigned long long a,
                                                    unsigned long long b,
                                                    unsigned long long c) {
    unsigned long long d;
    asm("fma.rn.f32x2 %0, %1, %2, %3;" : "=l"(d) : "l"(a), "l"(b), "l"(c));
    return d;
}

// ---------------------------------------------------------------------------
// Layer-1 node GEMM (K=6, tiny): fp32 SIMT, bf16 output.
// ---------------------------------------------------------------------------
template <int HC, int H>
__global__ __launch_bounds__(256)
void node_kernel(const float* __restrict__ hin, const float* __restrict__ pos,
                 const float* __restrict__ Wa, const float* __restrict__ ba,
                 __nv_bfloat16* __restrict__ A, int N) {
    constexpr int CIN  = HC + 3;
    constexpr int CINP = (CIN + 3) & ~3;
    extern __shared__ float sm[];
    float* Xs = sm;
    float* Ws = Xs + 128 * CINP;
    const int tid = threadIdx.x;
    const int n0  = blockIdx.x * 128;

    for (int idx = tid; idx < CINP * H; idx += 256) {
        int k = idx / H, c = idx - k * H;
        Ws[idx] = (k < CIN) ? Wa[k * H + c] : 0.f;
    }
    for (int idx = tid; idx < 128 * CINP; idx += 256) {
        int r = idx / CINP, k = idx - r * CINP;
        int n = n0 + r;
        float v = 0.f;
        if (n < N) {
            if (k < HC) v = hin[n * HC + k];
            else if (k < CIN) v = pos[n * 3 + (k - HC)];
        }
        Xs[idx] = v;
    }
    __syncthreads();

    const int tx = tid & 15, ty = tid >> 4;
    for (int cb = 0; cb < H; cb += 64) {
        unsigned long long acc[8][2];
#pragma unroll
        for (int j = 0; j < 2; ++j) {
            unsigned long long bv =
                *(const unsigned long long*)(ba + cb + 2 * (tx + 16 * j));
#pragma unroll
            for (int i = 0; i < 8; ++i) acc[i][j] = bv;
        }
#pragma unroll 4
        for (int k = 0; k < CINP; ++k) {
            unsigned long long w0 =
                *(const unsigned long long*)(Ws + k * H + cb + 2 * tx);
            unsigned long long w1 =
                *(const unsigned long long*)(Ws + k * H + cb + 2 * (tx + 16));
#pragma unroll
            for (int i = 0; i < 8; ++i) {
                float x = Xs[(ty + 16 * i) * CINP + k];
                unsigned long long xp = pk2(x, x);
                acc[i][0] = ffma2(xp, w0, acc[i][0]);
                acc[i][1] = ffma2(xp, w1, acc[i][1]);
            }
        }
#pragma unroll
        for (int i = 0; i < 8; ++i) {
            int n = n0 + ty + 16 * i;
            if (n < N) {
#pragma unroll
                for (int j = 0; j < 2; ++j) {
                    float lo, hi;
                    upk2(acc[i][j], lo, hi);
                    *(uint32_t*)(A + (size_t)n * H + cb + 2 * (tx + 16 * j)) =
                        pack_bf16(lo, hi);
                }
            }
        }
    }
}

// ---------------------------------------------------------------------------
// Node GEMM via WS-HMMA (1-term): A[n] = [h, pos, 1, pad] @ [Wa; ba; 0].
// ---------------------------------------------------------------------------
template <int HC, int H, int MAXB>
__global__ __launch_bounds__(256, MAXB)
void node_mma_kernel(const __nv_bfloat16* __restrict__ hin,
                     const float* __restrict__ pos,
                     const float* __restrict__ Wa, const float* __restrict__ ba,
                     __nv_bfloat16* __restrict__ A, int N, int tiles) {
    constexpr int CIN   = HC + 3;
    constexpr int KT    = ((HC + 4 + 15) / 16) * 16;  // 80 for HC=64
    constexpr int KC    = KT / 16;                     // 5
    constexpr int PAIRS = (KC + 1) / 2;                // 3 (last pair clamps)
    constexpr int RS    = KT * 2 + 16;
    constexpr int SX    = KT + 8;
    constexpr int NB    = H / 8;
    constexpr int PW    = 4;

    extern __shared__ char smem[];
    char* Xb[2] = {smem, smem + 128 * RS};
    __nv_bfloat16* Wh = (__nv_bfloat16*)(smem + 2 * 128 * RS);
    // NOTE: launcher allocates +256B slack after Wh (paired-B ldmatrix
    // lane-group 3 prefetch can address up to one row past the last n-block).

    const int tid = threadIdx.x, wid = tid >> 5, lane = tid & 31;
    const int r = lane >> 2, q = lane & 3;
    const bool isProd = wid < PW;

    for (int idx = tid; idx < KT * H; idx += 256) {
        int k = idx / H, c = idx - k * H;
        float w = (k < CIN) ? Wa[k * H + c] : ((k == CIN) ? ba[c] : 0.f);
        Wh[c * SX + k] = __float2bfloat16(w);
    }

    auto produce = [&](int t, char* Xbuf) {
        const int base = wid * 32;
#pragma unroll
        for (int p = 0; p < 16; ++p) {
            int row = base + 2 * p + (lane >> 4);
            int c4  = lane & 15;
            int n   = t * 128 + row;
            uint2 a = make_uint2(0u, 0u);
            if (n < N) a = *(const uint2*)(hin + (size_t)n * HC + 4 * c4);
            *(uint2*)(Xbuf + row * RS + c4 * 8) = a;
        }
#pragma unroll
        for (int p = 0; p < (KT - HC) / 4; ++p) {
            int row = base + lane;
            int n   = t * 128 + row;
            float4 v = make_float4(0.f, 0.f, 0.f, 0.f);
            if (p == 0) {
                int nn = (n < N) ? n : (N - 1);
                v.x = pos[nn * 3]; v.y = pos[nn * 3 + 1]; v.z = pos[nn * 3 + 2];
                v.w = 1.f;
            }
            *(uint2*)(Xbuf + row * RS + (HC / 4 + p) * 8) =
                make_uint2(pack_bf16(v.x, v.y), pack_bf16(v.z, v.w));
        }
    };

    auto consume = [&](int t, const char* Xbuf) {
        const int cw = wid - PW;
        const uint32_t Xu  = smem_u32(Xbuf);
        const uint32_t WhU = smem_u32(Wh);
        const int arow  = (lane & 7) + 8 * ((lane >> 3) & 1);
        const int ahalf = (lane >> 4) * 16;
        // B pair base: lane groups 0..3 -> (kc b0, kc b1, kc+1 b0, kc+1 b1)
        const uint32_t bbase = WhU + (uint32_t)((lane & 7) * SX * 2) +
                               (uint32_t)((lane >> 3) * 16);

        uint32_t ah[2][KC][4];
#pragma unroll
        for (int mt = 0; mt < 2; ++mt) {
            uint32_t abase = Xu +
                (uint32_t)((16 * (cw * 2 + mt) + arow) * RS) + ahalf;
#pragma unroll
            for (int kc = 0; kc < KC; ++kc)
                ldsm_x4(ah[mt][kc], abase + 32 * kc);
        }

        uint32_t bf[2][4];
        ldsm_x4(bf[0], bbase);  // nb=0, pair 0
#pragma unroll
        for (int nb = 0; nb < NB; ++nb) {
            float acc[2][2][4];
#pragma unroll
            for (int mt = 0; mt < 2; ++mt)
#pragma unroll
                for (int ch = 0; ch < 2; ++ch)
#pragma unroll
                    for (int i = 0; i < 4; ++i) acc[mt][ch][i] = 0.f;
#pragma unroll
            for (int pr = 0; pr < PAIRS; ++pr) {
                const int cur = (nb * PAIRS + pr) & 1;
                {
                    int nnb = nb, npr = pr + 1;
                    if (npr == PAIRS) { npr = 0; nnb = (nb + 1 < NB) ? nb + 1 : nb; }
                    uint32_t off = (uint32_t)(8 * nnb * SX * 2 +
                                              64 * min(npr, (KC - 1) / 2));
                    ldsm_x4(bf[cur ^ 1], bbase + off);
                }
                const uint32_t* b = bf[cur];
#pragma unroll
                for (int sub = 0; sub < 2; ++sub) {
                    int kc = 2 * pr + sub;
                    if (kc >= KC) break;
#pragma unroll
                    for (int mt = 0; mt < 2; ++mt)
                        mma16816(acc[mt][kc & 1], ah[mt][kc],
                                 b[2 * sub], b[2 * sub + 1]);
                }
            }
#pragma unroll
            for (int mt = 0; mt < 2; ++mt) {
                int nbase = t * 128 + 16 * (cw * 2 + mt);
                int col = 8 * nb + 2 * q;
                int nA = nbase + r, nBr = nbase + r + 8;
                if (nA < N)
                    *(uint32_t*)(A + (size_t)nA * H + col) =
                        pack_bf16(acc[mt][0][0] + acc[mt][1][0],
                                  acc[mt][0][1] + acc[mt][1][1]);
                if (nBr < N)
                    *(uint32_t*)(A + (size_t)nBr * H + col) =
                        pack_bf16(acc[mt][0][2] + acc[mt][1][2],
                                  acc[mt][0][3] + acc[mt][1][3]);
            }
        }
    };

    __syncthreads();
    const int t0 = blockIdx.x;
    if (isProd) produce(t0, Xb[0]);
    __syncthreads();

    for (int k = 0;; ++k) {
        int tc = t0 + k * gridDim.x;
        if (tc >= tiles) break;
        if (isProd) {
            int tp = tc + gridDim.x;
            if (tp < tiles) produce(tp, Xb[(k + 1) & 1]);
        } else {
            consume(tc, Xb[k & 1]);
        }
        __syncthreads();
    }
}

// ---------------------------------------------------------------------------
// Warp-specialized edge kernel (1-term): bf16 gather, sub/relu bf16x2,
// ldmatrix frags (B paired 2 kc per x4), fragment seg-max.
// ---------------------------------------------------------------------------
template <int H, int COUT, int TPB, int MAXB, bool OBF16>
__global__ __launch_bounds__(TPB, MAXB)
void edge_ws_kernel(const __nv_bfloat16* __restrict__ A,
                    const float* __restrict__ pos,
                    const int* __restrict__ src, const float* __restrict__ Wap,
                    const float* __restrict__ Wb, const float* __restrict__ bb,
                    void* __restrict__ hout, int N, int E, int tiles) {
    constexpr int WARPS = TPB / 32;
    constexpr int PW    = WARPS / 2;
    constexpr int NPN   = 2;
    constexpr int NODES = PW * NPN;
    constexpr int ROWS  = NODES * 16;
    constexpr int KC    = H / 16;       // even (4 or 8)
    constexpr int PAIRS = KC / 2;
    constexpr int NB    = COUT / 8;
    constexpr int RS    = H * 2 + 16;
    constexpr int SX    = H + 8;

    extern __shared__ char smem[];
    char* Xb[2] = {smem, smem + ROWS * RS};
    __nv_bfloat16* Wh = (__nv_bfloat16*)(smem + 2 * ROWS * RS);
    // launcher allocates +256B slack after Wh

    const int tid = threadIdx.x, wid = tid >> 5, lane = tid & 31;
    const bool isProd = wid < PW;

    for (int idx = tid; idx < H * COUT; idx += TPB) {
        int k = idx / COUT, n = idx - k * COUT;
        Wh[n * SX + k] = __float2bfloat16(Wb[idx]);
    }

    auto produce = [&](int t, char* Xbuf) {
        const int e0 = t * ROWS, n0t = t * NODES;
        const int pw = wid;
#pragma unroll
        for (int nn = 0; nn < NPN; ++nn) {
            const int g  = pw * NPN + nn;
            const int nd = min(n0t + g, N - 1);
            int e = e0 + 16 * g + (lane & 15);
            int srcv = (e < E) ? src[e] : 0;
            const int c4 = (H == 64) ? (lane & 15) : lane;
            float p0 = pos[nd * 3], p1 = pos[nd * 3 + 1], p2 = pos[nd * 3 + 2];
            float P0 = p0 * __ldg(&Wap[4 * c4 + 0]) + p1 * __ldg(&Wap[H + 4 * c4 + 0]) +
                       p2 * __ldg(&Wap[2 * H + 4 * c4 + 0]);
            float P1 = p0 * __ldg(&Wap[4 * c4 + 1]) + p1 * __ldg(&Wap[H + 4 * c4 + 1]) +
                       p2 * __ldg(&Wap[2 * H + 4 * c4 + 1]);
            float P2 = p0 * __ldg(&Wap[4 * c4 + 2]) + p1 * __ldg(&Wap[H + 4 * c4 + 2]) +
                       p2 * __ldg(&Wap[2 * H + 4 * c4 + 2]);
            float P3 = p0 * __ldg(&Wap[4 * c4 + 3]) + p1 * __ldg(&Wap[H + 4 * c4 + 3]) +
                       p2 * __ldg(&Wap[2 * H + 4 * c4 + 3]);
            uint32_t P01 = pack_bf16(P0, P1), P23 = pack_bf16(P2, P3);
            constexpr int PASSES = (H == 64) ? 8 : 16;
#pragma unroll
            for (int p = 0; p < PASSES; ++p) {
                int rowin = (H == 64) ? (2 * p + (lane >> 4)) : p;
                int j = __shfl_sync(0xffffffffu, srcv, rowin);
                uint2 av = *(const uint2*)(A + (size_t)j * H + 4 * c4);
                uint32_t x01 = sub_relu_bf16x2(av.x, P01);
                uint32_t x23 = sub_relu_bf16x2(av.y, P23);
                int row = 16 * g + rowin;
                *(uint2*)(Xbuf + row * RS + c4 * 8) = make_uint2(x01, x23);
            }
        }
    };

    auto consume = [&](int t, const char* Xbuf) {
        const int n0t = t * NODES;
        const int cw  = wid - PW;
        const uint32_t Xu  = smem_u32(Xbuf);
        const uint32_t WhU = smem_u32(Wh);
        const int arow  = (lane & 7) + 8 * ((lane >> 3) & 1);
        const int ahalf = (lane >> 4) * 16;
        const uint32_t bbase = WhU + (uint32_t)((lane & 7) * SX * 2) +
                               (uint32_t)((lane >> 3) * 16);

        uint32_t ah[NPN][KC][4];
#pragma unroll
        for (int nn = 0; nn < NPN; ++nn) {
            uint32_t abase = Xu +
                (uint32_t)((16 * (cw * NPN + nn) + arow) * RS) + ahalf;
#pragma unroll
            for (int kc = 0; kc < KC; ++kc)
                ldsm_x4(ah[nn][kc], abase + 32 * kc);
        }

        uint32_t bf[2][4];
        ldsm_x4(bf[0], bbase);
#pragma unroll
        for (int nb = 0; nb < NB; ++nb) {
            float acc[NPN][2][4];
#pragma unroll
            for (int nn = 0; nn < NPN; ++nn)
#pragma unroll
                for (int ch = 0; ch < 2; ++ch)
#pragma unroll
                    for (int i = 0; i < 4; ++i) acc[nn][ch][i] = 0.f;
#pragma unroll
            for (int pr = 0; pr < PAIRS; ++pr) {
                const int cur = (nb * PAIRS + pr) & 1;
                {
                    int nnb = nb, npr = pr + 1;
                    if (npr == PAIRS) { npr = 0; nnb = (nb + 1 < NB) ? nb + 1 : nb; }
                    ldsm_x4(bf[cur ^ 1],
                            bbase + (uint32_t)(8 * nnb * SX * 2 + 64 * npr));
                }
                const uint32_t* b = bf[cur];
#pragma unroll
                for (int sub = 0; sub < 2; ++sub) {
                    int kc = 2 * pr + sub;
#pragma unroll
                    for (int nn = 0; nn < NPN; ++nn)
                        mma16816(acc[nn][kc & 1], ah[nn][kc],
                                 b[2 * sub], b[2 * sub + 1]);
                }
            }
#pragma unroll
            for (int nn = 0; nn < NPN; ++nn) {
                float s0 = acc[nn][0][0] + acc[nn][1][0];
                float s1 = acc[nn][0][1] + acc[nn][1][1];
                float s2 = acc[nn][0][2] + acc[nn][1][2];
                float s3 = acc[nn][0][3] + acc[nn][1][3];
                float m0 = fmaxf(s0, s2);
                float m1 = fmaxf(s1, s3);
                m0 = fmaxf(m0, __shfl_xor_sync(0xffffffffu, m0, 4));
                m1 = fmaxf(m1, __shfl_xor_sync(0xffffffffu, m1, 4));
                m0 = fmaxf(m0, __shfl_xor_sync(0xffffffffu, m0, 8));
                m1 = fmaxf(m1, __shfl_xor_sync(0xffffffffu, m1, 8));
                m0 = fmaxf(m0, __shfl_xor_sync(0xffffffffu, m0, 16));
                m1 = fmaxf(m1, __shfl_xor_sync(0xffffffffu, m1, 16));
                int node = n0t + cw * NPN + nn;
                if (lane < 4 && node < N) {
                    int col = 8 * nb + 2 * lane;
                    float o0 = fmaxf(m0 + __ldg(&bb[col]), 0.f);
                    float o1 = fmaxf(m1 + __ldg(&bb[col + 1]), 0.f);
                    if (OBF16) {
                        *(uint32_t*)((__nv_bfloat16*)hout +
                                     (size_t)node * COUT + col) = pack_bf16(o0, o1);
                    } else {
                        *(float2*)((float*)hout + (size_t)node * COUT + col) =
                            make_float2(o0, o1);
                    }
                }
            }
        }
    };

    __syncthreads();
    const int t0 = blockIdx.x;
    if (isProd) produce(t0, Xb[0]);
    __syncthreads();

    for (int k = 0;; ++k) {
        int tc = t0 + k * gridDim.x;
        if (tc >= tiles) break;
        if (isProd) {
            int tp = tc + gridDim.x;
            if (tp < tiles) produce(tp, Xb[(k + 1) & 1]);
        } else {
            consume(tc, Xb[k & 1]);
        }
        __syncthreads();
    }
}

// ---------------------------------------------------------------------------
// Deterministic two-stage mean pool (batch sorted) + regressor.
// ---------------------------------------------------------------------------
__device__ __forceinline__ int lb(const int* __restrict__ b, int n, int v) {
    int lo = 0, hi = n;
    while (lo < hi) {
        int m = (lo + hi) >> 1;
        if (b[m] < v) lo = m + 1; else hi = m;
    }
    return lo;
}

__global__ void pool1_kernel(const float* __restrict__ h3,
                             const int* __restrict__ batch, int N,
                             float* __restrict__ part) {
    int b = blockIdx.x, k = blockIdx.y, c = threadIdx.x;
    int s = lb(batch, N, b), e = lb(batch, N, b + 1);
    int len = e - s;
    int cs = s + (int)(((long long)len * k) >> 3);
    int ce = s + (int)(((long long)len * (k + 1)) >> 3);
    float s0 = 0.f, s1 = 0.f, s2 = 0.f, s3 = 0.f;
    int n = cs;
    for (; n + 3 < ce; n += 4) {
        s0 += h3[(n + 0) * 128 + c];
        s1 += h3[(n + 1) * 128 + c];
        s2 += h3[(n + 2) * 128 + c];
        s3 += h3[(n + 3) * 128 + c];
    }
    for (; n < ce; ++n) s0 += h3[n * 128 + c];
    part[(b * 8 + k) * 128 + c] = ((s0 + s1) + (s2 + s3));
}

__global__ void pool2_kernel(const float* __restrict__ part,
                             const int* __restrict__ batch, int N,
                             float* __restrict__ pool) {
    int b = blockIdx.x, c = threadIdx.x;
    int s = lb(batch, N, b), e = lb(batch, N, b + 1);
    float sum = 0.f;
#pragma unroll
    for (int k = 0; k < 8; ++k) sum += part[(b * 8 + k) * 128 + c];
    pool[b * 128 + c] = sum / fmaxf((float)(e - s), 1.f);
}

__global__ void reg_kernel(const float* __restrict__ pool,
                           const float* __restrict__ wr1, const float* __restrict__ br1,
                           const float* __restrict__ wr2, const float* __restrict__ br2,
                           float* __restrict__ out, int B) {
    int b = blockIdx.x * blockDim.x + threadIdx.x;
    if (b >= B) return;
    float o = br2[0];
    for (int j = 0; j < 64; ++j) {
        float s = br1[j];
        for (int k = 0; k < 128; ++k) s += pool[b * 128 + k] * wr1[k * 64 + j];
        o += s * wr2[j];
    }
    out[b] = 1.f / (1.f + expf(-o));
}

extern "C" void kernel_launch(void* const* d_in, const int* in_sizes, int n_in,
                              void* d_out, int out_size) {
    const float* pos   = (const float*)d_in[0];
    const int*   ei    = (const int*)d_in[1];
    const int*   batch = (const int*)d_in[2];
    const float* w1a = (const float*)d_in[4],  *b1a = (const float*)d_in[5];
    const float* w1b = (const float*)d_in[6],  *b1b = (const float*)d_in[7];
    const float* w2a = (const float*)d_in[8],  *b2a = (const float*)d_in[9];
    const float* w2b = (const float*)d_in[10], *b2b = (const float*)d_in[11];
    const float* w3a = (const float*)d_in[12], *b3a = (const float*)d_in[13];
    const float* w3b = (const float*)d_in[14], *b3b = (const float*)d_in[15];
    const float* wr1 = (const float*)d_in[16], *br1 = (const float*)d_in[17];
    const float* wr2 = (const float*)d_in[18], *br2 = (const float*)d_in[19];
    float* out = (float*)d_out;

    int N = in_sizes[0] / 3;
    int E = in_sizes[1] / 2;
    int B = out_size;
    const int* srcp = ei;

    __nv_bfloat16 *Abuf, *h1, *h2;
    float *h3, *part, *pl;
    cudaGetSymbolAddress((void**)&Abuf, g_A);
    cudaGetSymbolAddress((void**)&h1, g_h1);
    cudaGetSymbolAddress((void**)&h2, g_h2);
    cudaGetSymbolAddress((void**)&h3, g_h3);
    cudaGetSymbolAddress((void**)&part, g_part);
    cudaGetSymbolAddress((void**)&pl, g_pool);

    // +256B slack after Wh in all MMA kernels (paired-B ldmatrix prefetch
    // overreach; see R15 fault analysis).
    const int smemN1 = (128 * 8 + 8 * 64) * 4;
    const int smemNM2 = 2 * 128 * 176 + 64 * 88 * 2 + 256;    //  56576
    const int smemNM3 = 2 * 128 * 176 + 128 * 88 * 2 + 256;   //  67840
    const int smemE12 = 2 * 128 * (64 * 2 + 16) + 64 * 72 * 2 + 256;    //  46336
    const int smemE3  = 2 * 256 * (128 * 2 + 16) + 128 * 136 * 2 + 256; // 174336

    cudaFuncSetAttribute(node_kernel<3, 64>,
                         cudaFuncAttributeMaxDynamicSharedMemorySize, smemN1);
    cudaFuncSetAttribute(node_mma_kernel<64, 64, 3>,
                         cudaFuncAttributeMaxDynamicSharedMemorySize, smemNM2);
    cudaFuncSetAttribute(node_mma_kernel<64, 128, 3>,
                         cudaFuncAttributeMaxDynamicSharedMemorySize, smemNM3);
    cudaFuncSetAttribute(edge_ws_kernel<64, 64, 256, 3, true>,
                         cudaFuncAttributeMaxDynamicSharedMemorySize, smemE12);
    cudaFuncSetAttribute(edge_ws_kernel<128, 128, 512, 1, false>,
                         cudaFuncAttributeMaxDynamicSharedMemorySize, smemE3);

    int tilesN = (N + 127) / 128;
    int tilesE12 = (E + 127) / 128;
    int tilesE3  = (E + 255) / 256;
    int gridN2 = tilesN < 444 ? tilesN : 444;
    int gridN3 = tilesN < 444 ? tilesN : 444;
    int grid12 = tilesE12 < 444 ? tilesE12 : 444;
    int grid3  = tilesE3 < 148 ? tilesE3 : 148;

    // layer 1 (h = pos)
    node_kernel<3, 64><<<tilesN, 256, smemN1>>>(pos, pos, w1a, b1a, Abuf, N);
    edge_ws_kernel<64, 64, 256, 3, true><<<grid12, 256, smemE12>>>(
        Abuf, pos, srcp, w1a + 3 * 64, w1b, b1b, h1, N, E, tilesE12);
    // layer 2
    node_mma_kernel<64, 64, 3><<<gridN2, 256, smemNM2>>>(
        h1, pos, w2a, b2a, Abuf, N, tilesN);
    edge_ws_kernel<64, 64, 256, 3, true><<<grid12, 256, smemE12>>>(
        Abuf, pos, srcp, w2a + 64 * 64, w2b, b2b, h2, N, E, tilesE12);
    // layer 3
    node_mma_kernel<64, 128, 3><<<gridN3, 256, smemNM3>>>(
        h2, pos, w3a, b3a, Abuf, N, tilesN);
    edge_ws_kernel<128, 128, 512, 1, false><<<grid3, 512, smemE3>>>(
        Abuf, pos, srcp, w3a + 64 * 128, w3b, b3b, h3, N, E, tilesE3);
    // pool + regressor
    pool1_kernel<<<dim3(B, 8), 128>>>(h3, batch, N, part);
    pool2_kernel<<<B, 128>>>(part, batch, N, pl);
    reg_kernel<<<1, 64>>>(pl, wr1, br1, wr2, br2, out, B);
}

// round 17
// speedup vs baseline: 1.1971x; 1.0209x over previous
#include <cuda_runtime.h>
#include <cuda_bf16.h>
#include <cstdint>
#include <math.h>

// ---------------------------------------------------------------------------
// BackbonePointNet on GB300, round 17 = R16 + non-MMA issue-stream cuts:
//  - P = pos@Wap precomputed per layer (g_P, bf16) -> producer loads one
//    uint4 per node instead of 12 ldg + 12 fma per lane.
//  - producer gather/sub-relu/STS vectorized to uint4 (halves mem ops).
//  - seg-max reduction packed bf16x2: 3 shfl + 3 max.bf16x2 (was 6+6).
// Engine: pure bf16 HMMA, paired-B ldmatrix, warp-specialized prod/cons,
// bf16 intermediates, K-folded node GEMMs. (rel_err 0.0 through R16.)
// ---------------------------------------------------------------------------

#define MAXN 100000
__device__ __nv_bfloat16 g_A[MAXN * 128];
__device__ __nv_bfloat16 g_P[MAXN * 128];
__device__ __nv_bfloat16 g_h1[MAXN * 64];
__device__ __nv_bfloat16 g_h2[MAXN * 64];
__device__ float g_h3[MAXN * 128];
__device__ float g_part[64 * 8 * 128];
__device__ float g_pool[64 * 128];

// --------------------------- small asm helpers ------------------------------
__device__ __forceinline__ void mma16816(float* c, const uint32_t* a,
                                         uint32_t b0, uint32_t b1) {
    asm volatile(
        "mma.sync.aligned.m16n8k16.row.col.f32.bf16.bf16.f32 "
        "{%0,%1,%2,%3}, {%4,%5,%6,%7}, {%8,%9}, {%0,%1,%2,%3};"
        : "+f"(c[0]), "+f"(c[1]), "+f"(c[2]), "+f"(c[3])
        : "r"(a[0]), "r"(a[1]), "r"(a[2]), "r"(a[3]), "r"(b0), "r"(b1));
}

__device__ __forceinline__ void ldsm_x4(uint32_t* d, uint32_t addr) {
    asm volatile(
        "ldmatrix.sync.aligned.m8n8.x4.shared.b16 {%0,%1,%2,%3}, [%4];"
        : "=r"(d[0]), "=r"(d[1]), "=r"(d[2]), "=r"(d[3]) : "r"(addr));
}

__device__ __forceinline__ uint32_t smem_u32(const void* p) {
    uint32_t a;
    asm("{ .reg .u64 t; cvta.to.shared.u64 t, %1; cvt.u32.u64 %0, t; }"
        : "=r"(a) : "l"(p));
    return a;
}

__device__ __forceinline__ uint32_t sub_relu_bf16x2(uint32_t a, uint32_t p) {
    uint32_t d;
    asm("sub.rn.bf16x2 %0, %1, %2;" : "=r"(d) : "r"(a), "r"(p));
    asm("max.bf16x2 %0, %1, %2;" : "=r"(d) : "r"(d), "r"(0u));
    return d;
}
__device__ __forceinline__ uint32_t max_bf16x2(uint32_t a, uint32_t b) {
    uint32_t d;
    asm("max.bf16x2 %0, %1, %2;" : "=r"(d) : "r"(a), "r"(b));
    return d;
}
__device__ __forceinline__ uint32_t pack_bf16(float a0, float a1) {
    uint32_t h;
    asm("cvt.rn.bf16x2.f32 %0, %1, %2;" : "=r"(h) : "f"(a1), "f"(a0));
    return h;
}

__device__ __forceinline__ unsigned long long pk2(float lo, float hi) {
    unsigned long long d;
    asm("mov.b64 %0, {%1, %2};" : "=l"(d)
        : "r"(__float_as_uint(lo)), "r"(__float_as_uint(hi)));
    return d;
}
__device__ __forceinline__ void upk2(unsigned long long v, float& lo, float& hi) {
    unsigned int a, b;
    asm("mov.b64 {%0, %1}, %2;" : "=r"(a), "=r"(b) : "l"(v));
    lo = __uint_as_float(a);
    hi = __uint_as_float(b);
}
__device__ __forceinline__ unsigned long long ffma2(unsigned long long a,
                                                    unsigned long long b,
                                                    unsigned long long c) {
    unsigned long long d;
    asm("fma.rn.f32x2 %0, %1, %2, %3;" : "=l"(d) : "l"(a), "l"(b), "l"(c));
    return d;
}

// ---------------------------------------------------------------------------
// P precompute: P[n][c] = pos[n] . Wap[:, c]  (bf16 out, pair per thread)
// ---------------------------------------------------------------------------
template <int H>
__global__ void pcomp_kernel(const float* __restrict__ pos,
                             const float* __restrict__ Wap,
                             __nv_bfloat16* __restrict__ P, int N) {
    int idx = blockIdx.x * blockDim.x + threadIdx.x;
    if (idx >= N * (H / 2)) return;
    int n = idx / (H / 2), c = (idx - n * (H / 2)) * 2;
    float p0 = pos[n * 3], p1 = pos[n * 3 + 1], p2 = pos[n * 3 + 2];
    float v0 = p0 * __ldg(&Wap[c]) + p1 * __ldg(&Wap[H + c]) +
               p2 * __ldg(&Wap[2 * H + c]);
    float v1 = p0 * __ldg(&Wap[c + 1]) + p1 * __ldg(&Wap[H + c + 1]) +
               p2 * __ldg(&Wap[2 * H + c + 1]);
    *(uint32_t*)(P + (size_t)n * H + c) = pack_bf16(v0, v1);
}

// ---------------------------------------------------------------------------
// Layer-1 node GEMM (K=6, tiny): fp32 SIMT, bf16 output.
// ---------------------------------------------------------------------------
template <int HC, int H>
__global__ __launch_bounds__(256)
void node_kernel(const float* __restrict__ hin, const float* __restrict__ pos,
                 const float* __restrict__ Wa, const float* __restrict__ ba,
                 __nv_bfloat16* __restrict__ A, int N) {
    constexpr int CIN  = HC + 3;
    constexpr int CINP = (CIN + 3) & ~3;
    extern __shared__ float sm[];
    float* Xs = sm;
    float* Ws = Xs + 128 * CINP;
    const int tid = threadIdx.x;
    const int n0  = blockIdx.x * 128;

    for (int idx = tid; idx < CINP * H; idx += 256) {
        int k = idx / H, c = idx - k * H;
        Ws[idx] = (k < CIN) ? Wa[k * H + c] : 0.f;
    }
    for (int idx = tid; idx < 128 * CINP; idx += 256) {
        int r = idx / CINP, k = idx - r * CINP;
        int n = n0 + r;
        float v = 0.f;
        if (n < N) {
            if (k < HC) v = hin[n * HC + k];
            else if (k < CIN) v = pos[n * 3 + (k - HC)];
        }
        Xs[idx] = v;
    }
    __syncthreads();

    const int tx = tid & 15, ty = tid >> 4;
    for (int cb = 0; cb < H; cb += 64) {
        unsigned long long acc[8][2];
#pragma unroll
        for (int j = 0; j < 2; ++j) {
            unsigned long long bv =
                *(const unsigned long long*)(ba + cb + 2 * (tx + 16 * j));
#pragma unroll
            for (int i = 0; i < 8; ++i) acc[i][j] = bv;
        }
#pragma unroll 4
        for (int k = 0; k < CINP; ++k) {
            unsigned long long w0 =
                *(const unsigned long long*)(Ws + k * H + cb + 2 * tx);
            unsigned long long w1 =
                *(const unsigned long long*)(Ws + k * H + cb + 2 * (tx + 16));
#pragma unroll
            for (int i = 0; i < 8; ++i) {
                float x = Xs[(ty + 16 * i) * CINP + k];
                unsigned long long xp = pk2(x, x);
                acc[i][0] = ffma2(xp, w0, acc[i][0]);
                acc[i][1] = ffma2(xp, w1, acc[i][1]);
            }
        }
#pragma unroll
        for (int i = 0; i < 8; ++i) {
            int n = n0 + ty + 16 * i;
            if (n < N) {
#pragma unroll
                for (int j = 0; j < 2; ++j) {
                    float lo, hi;
                    upk2(acc[i][j], lo, hi);
                    *(uint32_t*)(A + (size_t)n * H + cb + 2 * (tx + 16 * j)) =
                        pack_bf16(lo, hi);
                }
            }
        }
    }
}

// ---------------------------------------------------------------------------
// Node GEMM via WS-HMMA (1-term): A[n] = [h, pos, 1, pad] @ [Wa; ba; 0].
// ---------------------------------------------------------------------------
template <int HC, int H, int MAXB>
__global__ __launch_bounds__(256, MAXB)
void node_mma_kernel(const __nv_bfloat16* __restrict__ hin,
                     const float* __restrict__ pos,
                     const float* __restrict__ Wa, const float* __restrict__ ba,
                     __nv_bfloat16* __restrict__ A, int N, int tiles) {
    constexpr int CIN   = HC + 3;
    constexpr int KT    = ((HC + 4 + 15) / 16) * 16;  // 80 for HC=64
    constexpr int KC    = KT / 16;                     // 5
    constexpr int PAIRS = (KC + 1) / 2;                // 3 (last pair clamps)
    constexpr int RS    = KT * 2 + 16;
    constexpr int SX    = KT + 8;
    constexpr int NB    = H / 8;
    constexpr int PW    = 4;

    extern __shared__ char smem[];
    char* Xb[2] = {smem, smem + 128 * RS};
    __nv_bfloat16* Wh = (__nv_bfloat16*)(smem + 2 * 128 * RS);
    // launcher allocates +256B slack after Wh (paired-B ldmatrix overreach)

    const int tid = threadIdx.x, wid = tid >> 5, lane = tid & 31;
    const int r = lane >> 2, q = lane & 3;
    const bool isProd = wid < PW;

    for (int idx = tid; idx < KT * H; idx += 256) {
        int k = idx / H, c = idx - k * H;
        float w = (k < CIN) ? Wa[k * H + c] : ((k == CIN) ? ba[c] : 0.f);
        Wh[c * SX + k] = __float2bfloat16(w);
    }

    auto produce = [&](int t, char* Xbuf) {
        const int base = wid * 32;
#pragma unroll
        for (int p = 0; p < 16; ++p) {
            int row = base + 2 * p + (lane >> 4);
            int c4  = lane & 15;
            int n   = t * 128 + row;
            uint2 a = make_uint2(0u, 0u);
            if (n < N) a = *(const uint2*)(hin + (size_t)n * HC + 4 * c4);
            *(uint2*)(Xbuf + row * RS + c4 * 8) = a;
        }
#pragma unroll
        for (int p = 0; p < (KT - HC) / 4; ++p) {
            int row = base + lane;
            int n   = t * 128 + row;
            float4 v = make_float4(0.f, 0.f, 0.f, 0.f);
            if (p == 0) {
                int nn = (n < N) ? n : (N - 1);
                v.x = pos[nn * 3]; v.y = pos[nn * 3 + 1]; v.z = pos[nn * 3 + 2];
                v.w = 1.f;
            }
            *(uint2*)(Xbuf + row * RS + (HC / 4 + p) * 8) =
                make_uint2(pack_bf16(v.x, v.y), pack_bf16(v.z, v.w));
        }
    };

    auto consume = [&](int t, const char* Xbuf) {
        const int cw = wid - PW;
        const uint32_t Xu  = smem_u32(Xbuf);
        const uint32_t WhU = smem_u32(Wh);
        const int arow  = (lane & 7) + 8 * ((lane >> 3) & 1);
        const int ahalf = (lane >> 4) * 16;
        const uint32_t bbase = WhU + (uint32_t)((lane & 7) * SX * 2) +
                               (uint32_t)((lane >> 3) * 16);

        uint32_t ah[2][KC][4];
#pragma unroll
        for (int mt = 0; mt < 2; ++mt) {
            uint32_t abase = Xu +
                (uint32_t)((16 * (cw * 2 + mt) + arow) * RS) + ahalf;
#pragma unroll
            for (int kc = 0; kc < KC; ++kc)
                ldsm_x4(ah[mt][kc], abase + 32 * kc);
        }

        uint32_t bf[2][4];
        ldsm_x4(bf[0], bbase);
#pragma unroll
        for (int nb = 0; nb < NB; ++nb) {
            float acc[2][2][4];
#pragma unroll
            for (int mt = 0; mt < 2; ++mt)
#pragma unroll
                for (int ch = 0; ch < 2; ++ch)
#pragma unroll
                    for (int i = 0; i < 4; ++i) acc[mt][ch][i] = 0.f;
#pragma unroll
            for (int pr = 0; pr < PAIRS; ++pr) {
                const int cur = (nb * PAIRS + pr) & 1;
                {
                    int nnb = nb, npr = pr + 1;
                    if (npr == PAIRS) { npr = 0; nnb = (nb + 1 < NB) ? nb + 1 : nb; }
                    uint32_t off = (uint32_t)(8 * nnb * SX * 2 +
                                              64 * min(npr, (KC - 1) / 2));
                    ldsm_x4(bf[cur ^ 1], bbase + off);
                }
                const uint32_t* b = bf[cur];
#pragma unroll
                for (int sub = 0; sub < 2; ++sub) {
                    int kc = 2 * pr + sub;
                    if (kc >= KC) break;
#pragma unroll
                    for (int mt = 0; mt < 2; ++mt)
                        mma16816(acc[mt][kc & 1], ah[mt][kc],
                                 b[2 * sub], b[2 * sub + 1]);
                }
            }
#pragma unroll
            for (int mt = 0; mt < 2; ++mt) {
                int nbase = t * 128 + 16 * (cw * 2 + mt);
                int col = 8 * nb + 2 * q;
                int nA = nbase + r, nBr = nbase + r + 8;
                if (nA < N)
                    *(uint32_t*)(A + (size_t)nA * H + col) =
                        pack_bf16(acc[mt][0][0] + acc[mt][1][0],
                                  acc[mt][0][1] + acc[mt][1][1]);
                if (nBr < N)
                    *(uint32_t*)(A + (size_t)nBr * H + col) =
                        pack_bf16(acc[mt][0][2] + acc[mt][1][2],
                                  acc[mt][0][3] + acc[mt][1][3]);
            }
        }
    };

    __syncthreads();
    const int t0 = blockIdx.x;
    if (isProd) produce(t0, Xb[0]);
    __syncthreads();

    for (int k = 0;; ++k) {
        int tc = t0 + k * gridDim.x;
        if (tc >= tiles) break;
        if (isProd) {
            int tp = tc + gridDim.x;
            if (tp < tiles) produce(tp, Xb[(k + 1) & 1]);
        } else {
            consume(tc, Xb[k & 1]);
        }
        __syncthreads();
    }
}

// ---------------------------------------------------------------------------
// Warp-specialized edge kernel (1-term, precomputed P, uint4 producer,
// packed-bf16 seg-max reduction).
// ---------------------------------------------------------------------------
template <int H, int COUT, int TPB, int MAXB, bool OBF16>
__global__ __launch_bounds__(TPB, MAXB)
void edge_ws_kernel(const __nv_bfloat16* __restrict__ A,
                    const __nv_bfloat16* __restrict__ Pt,
                    const int* __restrict__ src,
                    const float* __restrict__ Wb, const float* __restrict__ bb,
                    void* __restrict__ hout, int N, int E, int tiles) {
    constexpr int WARPS = TPB / 32;
    constexpr int PW    = WARPS / 2;
    constexpr int NPN   = 2;
    constexpr int NODES = PW * NPN;
    constexpr int ROWS  = NODES * 16;
    constexpr int KC    = H / 16;       // even (4 or 8)
    constexpr int PAIRS = KC / 2;
    constexpr int NB    = COUT / 8;
    constexpr int RS    = H * 2 + 16;
    constexpr int SX    = H + 8;

    extern __shared__ char smem[];
    char* Xb[2] = {smem, smem + ROWS * RS};
    __nv_bfloat16* Wh = (__nv_bfloat16*)(smem + 2 * ROWS * RS);
    // launcher allocates +256B slack after Wh

    const int tid = threadIdx.x, wid = tid >> 5, lane = tid & 31;
    const bool isProd = wid < PW;

    for (int idx = tid; idx < H * COUT; idx += TPB) {
        int k = idx / COUT, n = idx - k * COUT;
        Wh[n * SX + k] = __float2bfloat16(Wb[idx]);
    }

    auto produce = [&](int t, char* Xbuf) {
        const int e0 = t * ROWS, n0t = t * NODES;
        constexpr int LPR = H / 8;       // lanes per row (8 or 16)
        constexpr int RPP = 32 / LPR;    // rows per pass (4 or 2)
        constexpr int PASSES = 16 / RPP; // 4 or 8
        const int c8 = lane % LPR;
        const int rsub = lane / LPR;
#pragma unroll
        for (int nn = 0; nn < NPN; ++nn) {
            const int g  = wid * NPN + nn;
            const int nd = min(n0t + g, N - 1);
            int e = e0 + 16 * g + (lane & 15);
            int srcv = (e < E) ? src[e] : 0;
            uint4 Pv = *(const uint4*)(Pt + (size_t)nd * H + 8 * c8);
#pragma unroll
            for (int p = 0; p < PASSES; ++p) {
                int rowin = RPP * p + rsub;
                int j = __shfl_sync(0xffffffffu, srcv, rowin);
                uint4 av = *(const uint4*)(A + (size_t)j * H + 8 * c8);
                uint4 x;
                x.x = sub_relu_bf16x2(av.x, Pv.x);
                x.y = sub_relu_bf16x2(av.y, Pv.y);
                x.z = sub_relu_bf16x2(av.z, Pv.z);
                x.w = sub_relu_bf16x2(av.w, Pv.w);
                *(uint4*)(Xbuf + (16 * g + rowin) * RS + c8 * 16) = x;
            }
        }
    };

    auto consume = [&](int t, const char* Xbuf) {
        const int n0t = t * NODES;
        const int cw  = wid - PW;
        const uint32_t Xu  = smem_u32(Xbuf);
        const uint32_t WhU = smem_u32(Wh);
        const int arow  = (lane & 7) + 8 * ((lane >> 3) & 1);
        const int ahalf = (lane >> 4) * 16;
        const uint32_t bbase = WhU + (uint32_t)((lane & 7) * SX * 2) +
                               (uint32_t)((lane >> 3) * 16);

        uint32_t ah[NPN][KC][4];
#pragma unroll
        for (int nn = 0; nn < NPN; ++nn) {
            uint32_t abase = Xu +
                (uint32_t)((16 * (cw * NPN + nn) + arow) * RS) + ahalf;
#pragma unroll
            for (int kc = 0; kc < KC; ++kc)
                ldsm_x4(ah[nn][kc], abase + 32 * kc);
        }

        uint32_t bf[2][4];
        ldsm_x4(bf[0], bbase);
#pragma unroll
        for (int nb = 0; nb < NB; ++nb) {
            float acc[NPN][2][4];
#pragma unroll
            for (int nn = 0; nn < NPN; ++nn)
#pragma unroll
                for (int ch = 0; ch < 2; ++ch)
#pragma unroll
                    for (int i = 0; i < 4; ++i) acc[nn][ch][i] = 0.f;
#pragma unroll
            for (int pr = 0; pr < PAIRS; ++pr) {
                const int cur = (nb * PAIRS + pr) & 1;
                {
                    int nnb = nb, npr = pr + 1;
                    if (npr == PAIRS) { npr = 0; nnb = (nb + 1 < NB) ? nb + 1 : nb; }
                    ldsm_x4(bf[cur ^ 1],
                            bbase + (uint32_t)(8 * nnb * SX * 2 + 64 * npr));
                }
                const uint32_t* b = bf[cur];
#pragma unroll
                for (int sub = 0; sub < 2; ++sub) {
                    int kc = 2 * pr + sub;
#pragma unroll
                    for (int nn = 0; nn < NPN; ++nn)
                        mma16816(acc[nn][kc & 1], ah[nn][kc],
                                 b[2 * sub], b[2 * sub + 1]);
                }
            }
#pragma unroll
            for (int nn = 0; nn < NPN; ++nn) {
                float m0f = fmaxf(acc[nn][0][0] + acc[nn][1][0],
                                  acc[nn][0][2] + acc[nn][1][2]);
                float m1f = fmaxf(acc[nn][0][1] + acc[nn][1][1],
                                  acc[nn][0][3] + acc[nn][1][3]);
                uint32_t m = pack_bf16(m0f, m1f);
                m = max_bf16x2(m, __shfl_xor_sync(0xffffffffu, m, 4));
                m = max_bf16x2(m, __shfl_xor_sync(0xffffffffu, m, 8));
                m = max_bf16x2(m, __shfl_xor_sync(0xffffffffu, m, 16));
                int node = n0t + cw * NPN + nn;
                if (lane < 4 && node < N) {
                    int col = 8 * nb + 2 * lane;
                    float o0 = fmaxf(__uint_as_float(m << 16) +
                                     __ldg(&bb[col]), 0.f);
                    float o1 = fmaxf(__uint_as_float(m & 0xffff0000u) +
                                     __ldg(&bb[col + 1]), 0.f);
                    if (OBF16) {
                        *(uint32_t*)((__nv_bfloat16*)hout +
                                     (size_t)node * COUT + col) = pack_bf16(o0, o1);
                    } else {
                        *(float2*)((float*)hout + (size_t)node * COUT + col) =
                            make_float2(o0, o1);
                    }
                }
            }
        }
    };

    __syncthreads();
    const int t0 = blockIdx.x;
    if (isProd) produce(t0, Xb[0]);
    __syncthreads();

    for (int k = 0;; ++k) {
        int tc = t0 + k * gridDim.x;
        if (tc >= tiles) break;
        if (isProd) {
            int tp = tc + gridDim.x;
            if (tp < tiles) produce(tp, Xb[(k + 1) & 1]);
        } else {
            consume(tc, Xb[k & 1]);
        }
        __syncthreads();
    }
}

// ---------------------------------------------------------------------------
// Deterministic two-stage mean pool (batch sorted) + regressor.
// ---------------------------------------------------------------------------
__device__ __forceinline__ int lb(const int* __restrict__ b, int n, int v) {
    int lo = 0, hi = n;
    while (lo < hi) {
        int m = (lo + hi) >> 1;
        if (b[m] < v) lo = m + 1; else hi = m;
    }
    return lo;
}

__global__ void pool1_kernel(const float* __restrict__ h3,
                             const int* __restrict__ batch, int N,
                             float* __restrict__ part) {
    int b = blockIdx.x, k = blockIdx.y, c = threadIdx.x;
    int s = lb(batch, N, b), e = lb(batch, N, b + 1);
    int len = e - s;
    int cs = s + (int)(((long long)len * k) >> 3);
    int ce = s + (int)(((long long)len * (k + 1)) >> 3);
    float s0 = 0.f, s1 = 0.f, s2 = 0.f, s3 = 0.f;
    int n = cs;
    for (; n + 3 < ce; n += 4) {
        s0 += h3[(n + 0) * 128 + c];
        s1 += h3[(n + 1) * 128 + c];
        s2 += h3[(n + 2) * 128 + c];
        s3 += h3[(n + 3) * 128 + c];
    }
    for (; n < ce; ++n) s0 += h3[n * 128 + c];
    part[(b * 8 + k) * 128 + c] = ((s0 + s1) + (s2 + s3));
}

__global__ void pool2_kernel(const float* __restrict__ part,
                             const int* __restrict__ batch, int N,
                             float* __restrict__ pool) {
    int b = blockIdx.x, c = threadIdx.x;
    int s = lb(batch, N, b), e = lb(batch, N, b + 1);
    float sum = 0.f;
#pragma unroll
    for (int k = 0; k < 8; ++k) sum += part[(b * 8 + k) * 128 + c];
    pool[b * 128 + c] = sum / fmaxf((float)(e - s), 1.f);
}

__global__ void reg_kernel(const float* __restrict__ pool,
                           const float* __restrict__ wr1, const float* __restrict__ br1,
                           const float* __restrict__ wr2, const float* __restrict__ br2,
                           float* __restrict__ out, int B) {
    int b = blockIdx.x * blockDim.x + threadIdx.x;
    if (b >= B) return;
    float o = br2[0];
    for (int j = 0; j < 64; ++j) {
        float s = br1[j];
        for (int k = 0; k < 128; ++k) s += pool[b * 128 + k] * wr1[k * 64 + j];
        o += s * wr2[j];
    }
    out[b] = 1.f / (1.f + expf(-o));
}

extern "C" void kernel_launch(void* const* d_in, const int* in_sizes, int n_in,
                              void* d_out, int out_size) {
    const float* pos   = (const float*)d_in[0];
    const int*   ei    = (const int*)d_in[1];
    const int*   batch = (const int*)d_in[2];
    const float* w1a = (const float*)d_in[4],  *b1a = (const float*)d_in[5];
    const float* w1b = (const float*)d_in[6],  *b1b = (const float*)d_in[7];
    const float* w2a = (const float*)d_in[8],  *b2a = (const float*)d_in[9];
    const float* w2b = (const float*)d_in[10], *b2b = (const float*)d_in[11];
    const float* w3a = (const float*)d_in[12], *b3a = (const float*)d_in[13];
    const float* w3b = (const float*)d_in[14], *b3b = (const float*)d_in[15];
    const float* wr1 = (const float*)d_in[16], *br1 = (const float*)d_in[17];
    const float* wr2 = (const float*)d_in[18], *br2 = (const float*)d_in[19];
    float* out = (float*)d_out;

    int N = in_sizes[0] / 3;
    int E = in_sizes[1] / 2;
    int B = out_size;
    const int* srcp = ei;

    __nv_bfloat16 *Abuf, *Pbuf, *h1, *h2;
    float *h3, *part, *pl;
    cudaGetSymbolAddress((void**)&Abuf, g_A);
    cudaGetSymbolAddress((void**)&Pbuf, g_P);
    cudaGetSymbolAddress((void**)&h1, g_h1);
    cudaGetSymbolAddress((void**)&h2, g_h2);
    cudaGetSymbolAddress((void**)&h3, g_h3);
    cudaGetSymbolAddress((void**)&part, g_part);
    cudaGetSymbolAddress((void**)&pl, g_pool);

    const int smemN1 = (128 * 8 + 8 * 64) * 4;
    const int smemNM2 = 2 * 128 * 176 + 64 * 88 * 2 + 256;
    const int smemNM3 = 2 * 128 * 176 + 128 * 88 * 2 + 256;
    const int smemE12 = 2 * 128 * (64 * 2 + 16) + 64 * 72 * 2 + 256;
    const int smemE3  = 2 * 256 * (128 * 2 + 16) + 128 * 136 * 2 + 256;

    cudaFuncSetAttribute(node_kernel<3, 64>,
                         cudaFuncAttributeMaxDynamicSharedMemorySize, smemN1);
    cudaFuncSetAttribute(node_mma_kernel<64, 64, 3>,
                         cudaFuncAttributeMaxDynamicSharedMemorySize, smemNM2);
    cudaFuncSetAttribute(node_mma_kernel<64, 128, 3>,
                         cudaFuncAttributeMaxDynamicSharedMemorySize, smemNM3);
    cudaFuncSetAttribute(edge_ws_kernel<64, 64, 256, 3, true>,
                         cudaFuncAttributeMaxDynamicSharedMemorySize, smemE12);
    cudaFuncSetAttribute(edge_ws_kernel<128, 128, 512, 1, false>,
                         cudaFuncAttributeMaxDynamicSharedMemorySize, smemE3);

    int tilesN = (N + 127) / 128;
    int tilesE12 = (E + 127) / 128;
    int tilesE3  = (E + 255) / 256;
    int gridN2 = tilesN < 444 ? tilesN : 444;
    int gridN3 = tilesN < 444 ? tilesN : 444;
    int grid12 = tilesE12 < 444 ? tilesE12 : 444;
    int grid3  = tilesE3 < 148 ? tilesE3 : 148;
    int pgrid64  = (N * 32 + 255) / 256;
    int pgrid128 = (N * 64 + 255) / 256;

    // layer 1 (h = pos)
    node_kernel<3, 64><<<tilesN, 256, smemN1>>>(pos, pos, w1a, b1a, Abuf, N);
    pcomp_kernel<64><<<pgrid64, 256>>>(pos, w1a + 3 * 64, Pbuf, N);
    edge_ws_kernel<64, 64, 256, 3, true><<<grid12, 256, smemE12>>>(
        Abuf, Pbuf, srcp, w1b, b1b, h1, N, E, tilesE12);
    // layer 2
    node_mma_kernel<64, 64, 3><<<gridN2, 256, smemNM2>>>(
        h1, pos, w2a, b2a, Abuf, N, tilesN);
    pcomp_kernel<64><<<pgrid64, 256>>>(pos, w2a + 64 * 64, Pbuf, N);
    edge_ws_kernel<64, 64, 256, 3, true><<<grid12, 256, smemE12>>>(
        Abuf, Pbuf, srcp, w2b, b2b, h2, N, E, tilesE12);
    // layer 3
    node_mma_kernel<64, 128, 3><<<gridN3, 256, smemNM3>>>(
        h2, pos, w3a, b3a, Abuf, N, tilesN);
    pcomp_kernel<128><<<pgrid128, 256>>>(pos, w3a + 64 * 128, Pbuf, N);
    edge_ws_kernel<128, 128, 512, 1, false><<<grid3, 512, smemE3>>>(
        Abuf, Pbuf, srcp, w3b, b3b, h3, N, E, tilesE3);
    // pool + regressor
    pool1_kernel<<<dim3(B, 8), 128>>>(h3, batch, N, part);
    pool2_kernel<<<B, 128>>>(part, batch, N, pl);
    reg_kernel<<<1, 64>>>(pl, wr1, br1, wr2, br2, out, B);
}